// round 5
// baseline (speedup 1.0000x reference)
#include <cuda_runtime.h>
#include <cuda_bf16.h>
#include <cstdint>

// Segment-sum: feat [N, 128] f32, sorted segment_ids [N] i32 -> out [G, 128] f32.
// cp.async pipelined: each warp owns a contiguous row range; lane l owns columns
// [4l, 4l+4). Rows stream through a per-warp smem ring (depth D) via cp.async.cg,
// decoupling in-flight DRAM bytes from register count. Flush accumulators with
// atomicAdd only at segment boundaries.

#define PIPE_D 8          // ring depth (rows in flight per warp)
#define WARPS_PER_BLOCK 8

__global__ void zero_out_kernel(float4* out, int n4) {
    int i = blockIdx.x * blockDim.x + threadIdx.x;
    int stride = gridDim.x * blockDim.x;
    float4 z = make_float4(0.f, 0.f, 0.f, 0.f);
    for (; i < n4; i += stride) out[i] = z;
}

__device__ __forceinline__ void flush_acc(float* __restrict__ out, int seg, int lane,
                                          const float4& a) {
    float* p = out + (size_t)seg * 128 + lane * 4;
    atomicAdd(p + 0, a.x);
    atomicAdd(p + 1, a.y);
    atomicAdd(p + 2, a.z);
    atomicAdd(p + 3, a.w);
}

__device__ __forceinline__ void cp_async16(uint32_t smem_addr, const void* gmem) {
    asm volatile("cp.async.cg.shared.global [%0], [%1], 16;\n"
                 :: "r"(smem_addr), "l"(gmem) : "memory");
}
__device__ __forceinline__ void cp_commit() {
    asm volatile("cp.async.commit_group;\n" ::: "memory");
}
__device__ __forceinline__ void cp_wait() {
    asm volatile("cp.async.wait_group %0;\n" :: "n"(PIPE_D - 1) : "memory");
}

__global__ __launch_bounds__(256, 6) void segsum_kernel(
    const float4* __restrict__ feat,      // [N, 32] float4
    const int* __restrict__ seg_ids,      // [N]
    float* __restrict__ out,              // [G, 128]
    int n_rows)
{
    // Per-warp ring: PIPE_D rows x 32 lanes x 16B = 4KB/warp, 32KB/block.
    __shared__ float4 ring[WARPS_PER_BLOCK][PIPE_D][32];

    const int lane = threadIdx.x & 31;
    const int wib = threadIdx.x >> 5;     // warp in block
    const int warp = (blockIdx.x * blockDim.x + threadIdx.x) >> 5;
    const int nwarps = (gridDim.x * blockDim.x) >> 5;

    const int rows_per = (n_rows + nwarps - 1) / nwarps;
    long start = (long)warp * rows_per;
    long end = start + rows_per;
    if (end > n_rows) end = n_rows;
    if (start >= end) return;
    const long len = end - start;

    uint32_t ring_base;
    {
        const void* p = &ring[wib][0][lane];
        asm("{ .reg .u64 t; cvta.to.shared.u64 t, %1; cvt.u32.u64 %0, t; }"
            : "=r"(ring_base) : "l"(p));
    }
    // slot d address = ring_base + d * 32 * 16
    #define SLOT_ADDR(d) (ring_base + (uint32_t)(d) * (32u * 16u))

    // Prologue: commit PIPE_D groups (cp.async for real rows, empty otherwise).
    #pragma unroll
    for (int d = 0; d < PIPE_D; ++d) {
        if (d < len) cp_async16(SLOT_ADDR(d), &feat[(start + d) * 32 + lane]);
        cp_commit();
    }

    float4 acc = make_float4(0.f, 0.f, 0.f, 0.f);
    int cur = __ldg(&seg_ids[start]);

    for (long i = 0; i < len; ++i) {
        cp_wait();   // group i complete (committed = PIPE_D + i, keep <= D-1 pending)

        int slot = (int)(i & (PIPE_D - 1));
        float4 v = ring[wib][slot][lane];
        int s = __ldg(&seg_ids[start + i]);

        if (s != cur) {
            flush_acc(out, cur, lane, acc);
            acc = make_float4(0.f, 0.f, 0.f, 0.f);
            cur = s;
        }
        acc.x += v.x; acc.y += v.y; acc.z += v.z; acc.w += v.w;

        // Prefetch row i + D into the slot we just freed; always commit.
        long nxt = i + PIPE_D;
        if (nxt < len) cp_async16(SLOT_ADDR(slot), &feat[(start + nxt) * 32 + lane]);
        cp_commit();
    }
    flush_acc(out, cur, lane, acc);
    #undef SLOT_ADDR
}

extern "C" void kernel_launch(void* const* d_in, const int* in_sizes, int n_in,
                              void* d_out, int out_size) {
    const float4* feat = (const float4*)d_in[0];       // [N,128] f32
    const int* seg_ids = (const int*)d_in[1];          // [N] i32
    float* out = (float*)d_out;

    int n_rows = in_sizes[1];   // number of nodes

    // Zero the output (poisoned to 0xAA by harness).
    int n4 = out_size / 4;
    zero_out_kernel<<<(n4 + 255) / 256, 256>>>((float4*)d_out, n4);

    // One exact wave: 148 SMs x 6 blocks (32KB smem/block -> 192KB/SM).
    int nblocks = 148 * 6;
    segsum_kernel<<<nblocks, 256>>>(feat, seg_ids, out, n_rows);
}